// round 10
// baseline (speedup 1.0000x reference)
#include <cuda_runtime.h>

// Causal GQA flash attention, TF32 mma.sync path.
// B=2, S=2048, H=32, Hkv=8, D=128, fp32 in/out.

namespace {

constexpr int S     = 2048;
constexpr int NH    = 32;
constexpr int NKV   = 8;
constexpr int HD    = 128;
constexpr int BQ    = 128;   // query rows per CTA (16 per warp, 8 warps)
constexpr int BK    = 64;    // key rows per tile
constexpr int QSTR  = 132;   // smem strides (floats), chosen conflict-free
constexpr int KSTR  = 132;
constexpr int VSTR  = 136;
constexpr int PSTR  = 68;
constexpr float SCALE = 0.08838834764831844f;  // 128^-0.5

constexpr int SMEM_FLOATS = BQ * QSTR + BK * KSTR + BK * VSTR + 8 * 16 * PSTR;

__device__ __forceinline__ unsigned f2tf(float f) {
    unsigned u;
    asm("cvt.rna.tf32.f32 %0, %1;" : "=r"(u) : "f"(f));
    return u;
}

__device__ __forceinline__ void mma8(float c[4], const unsigned a[4], const unsigned b[2]) {
    asm volatile(
        "mma.sync.aligned.m16n8k8.row.col.f32.tf32.tf32.f32 "
        "{%0,%1,%2,%3}, {%4,%5,%6,%7}, {%8,%9}, {%0,%1,%2,%3};\n"
        : "+f"(c[0]), "+f"(c[1]), "+f"(c[2]), "+f"(c[3])
        : "r"(a[0]), "r"(a[1]), "r"(a[2]), "r"(a[3]), "r"(b[0]), "r"(b[1]));
}

__global__ void __launch_bounds__(256, 1)
fa_tf32_kernel(const float* __restrict__ Qg, const float* __restrict__ Kg,
               const float* __restrict__ Vg, float* __restrict__ Out) {
    extern __shared__ float smem[];
    float* Qs = smem;                   // BQ x QSTR
    float* Ks = Qs + BQ * QSTR;        // BK x KSTR
    float* Vs = Ks + BK * KSTR;        // BK x VSTR
    float* Ps = Vs + BK * VSTR;        // 8 warps * 16 x PSTR

    const int bid = blockIdx.x;
    const int qbi = 15 - (bid & 15);   // heavy (long-loop) Q blocks launch first
    const int h   = (bid >> 4) & 31;
    const int b   = bid >> 9;
    const int hkv = h >> 2;            // n_rep = 4
    const int q0  = qbi * BQ;

    const int tid  = threadIdx.x;
    const int warp = tid >> 5;
    const int lane = tid & 31;
    const int g = lane >> 2;           // groupID   (0..7)
    const int t = lane & 3;            // threadID_in_group (0..3)

    const float* qg = Qg + (b * S + q0) * (NH * HD) + h * HD;
    const float* kg = Kg + b * S * (NKV * HD) + hkv * HD;
    const float* vg = Vg + b * S * (NKV * HD) + hkv * HD;

    // ---- Load + scale + tf32-round Q tile ----
    #pragma unroll
    for (int i = 0; i < 16; i++) {
        int lin = (tid + 256 * i) << 2;       // float index in 128x128 tile
        int row = lin >> 7;
        int col = lin & 127;
        float4 x = *reinterpret_cast<const float4*>(qg + row * (NH * HD) + col);
        uint4 u;
        u.x = f2tf(x.x * SCALE);
        u.y = f2tf(x.y * SCALE);
        u.z = f2tf(x.z * SCALE);
        u.w = f2tf(x.w * SCALE);
        *reinterpret_cast<uint4*>(Qs + row * QSTR + col) = u;
    }

    float Oa[16][4];
    #pragma unroll
    for (int i = 0; i < 16; i++)
        Oa[i][0] = Oa[i][1] = Oa[i][2] = Oa[i][3] = 0.f;
    float m_lo = -1e30f, m_hi = -1e30f, l_lo = 0.f, l_hi = 0.f;

    unsigned* Pw = reinterpret_cast<unsigned*>(Ps) + warp * 16 * PSTR;
    const unsigned* Qu = reinterpret_cast<const unsigned*>(Qs);
    const unsigned* Ku = reinterpret_cast<const unsigned*>(Ks);
    const unsigned* Vu = reinterpret_cast<const unsigned*>(Vs);

    const int jb_end = 2 * qbi + 1;
    const int qw = q0 + warp * 16;     // this warp's first query row

    for (int jb = 0; jb <= jb_end; jb++) {
        __syncthreads();               // previous tile fully consumed
        // ---- Load + tf32-round K,V tiles (64x128 each) ----
        #pragma unroll
        for (int i = 0; i < 8; i++) {
            int lin = (tid + 256 * i) << 2;
            int row = lin >> 7;
            int col = lin & 127;
            int grow = jb * BK + row;
            float4 x = *reinterpret_cast<const float4*>(kg + grow * (NKV * HD) + col);
            uint4 u;
            u.x = f2tf(x.x); u.y = f2tf(x.y); u.z = f2tf(x.z); u.w = f2tf(x.w);
            *reinterpret_cast<uint4*>(Ks + row * KSTR + col) = u;
            float4 y = *reinterpret_cast<const float4*>(vg + grow * (NKV * HD) + col);
            uint4 w;
            w.x = f2tf(y.x); w.y = f2tf(y.y); w.z = f2tf(y.z); w.w = f2tf(y.w);
            *reinterpret_cast<uint4*>(Vs + row * VSTR + col) = w;
        }
        __syncthreads();

        if (jb * BK > qw + 15) continue;   // tile entirely above causal diag for this warp

        // ---- S = Q K^T (16x64 per warp) ----
        float sc[8][4];
        #pragma unroll
        for (int nt = 0; nt < 8; nt++)
            sc[nt][0] = sc[nt][1] = sc[nt][2] = sc[nt][3] = 0.f;

        const int qrow = warp * 16 + g;
        #pragma unroll
        for (int ks = 0; ks < 16; ks++) {
            unsigned a[4];
            int c0 = ks * 8 + t;
            a[0] = Qu[qrow * QSTR + c0];
            a[1] = Qu[(qrow + 8) * QSTR + c0];
            a[2] = Qu[qrow * QSTR + c0 + 4];
            a[3] = Qu[(qrow + 8) * QSTR + c0 + 4];
            #pragma unroll
            for (int nt = 0; nt < 8; nt++) {
                unsigned bb[2];
                bb[0] = Ku[(nt * 8 + g) * KSTR + c0];
                bb[1] = Ku[(nt * 8 + g) * KSTR + c0 + 4];
                mma8(sc[nt], a, bb);
            }
        }

        // ---- Causal mask (only when tile crosses the diagonal band) ----
        const int qr_lo = qw + g;
        const int qr_hi = qr_lo + 8;
        if (jb * BK + BK - 1 > qw) {
            #pragma unroll
            for (int nt = 0; nt < 8; nt++) {
                int kc = jb * BK + nt * 8 + 2 * t;
                if (kc > qr_lo)     sc[nt][0] = -1e30f;
                if (kc + 1 > qr_lo) sc[nt][1] = -1e30f;
                if (kc > qr_hi)     sc[nt][2] = -1e30f;
                if (kc + 1 > qr_hi) sc[nt][3] = -1e30f;
            }
        }

        // ---- Online softmax (fp32) ----
        float mx_lo = -1e30f, mx_hi = -1e30f;
        #pragma unroll
        for (int nt = 0; nt < 8; nt++) {
            mx_lo = fmaxf(mx_lo, fmaxf(sc[nt][0], sc[nt][1]));
            mx_hi = fmaxf(mx_hi, fmaxf(sc[nt][2], sc[nt][3]));
        }
        mx_lo = fmaxf(mx_lo, __shfl_xor_sync(0xffffffffu, mx_lo, 1));
        mx_lo = fmaxf(mx_lo, __shfl_xor_sync(0xffffffffu, mx_lo, 2));
        mx_hi = fmaxf(mx_hi, __shfl_xor_sync(0xffffffffu, mx_hi, 1));
        mx_hi = fmaxf(mx_hi, __shfl_xor_sync(0xffffffffu, mx_hi, 2));
        float mn_lo = fmaxf(m_lo, mx_lo);
        float mn_hi = fmaxf(m_hi, mx_hi);
        float al_lo = __expf(m_lo - mn_lo);
        float al_hi = __expf(m_hi - mn_hi);
        m_lo = mn_lo; m_hi = mn_hi;

        float s_lo = 0.f, s_hi = 0.f;
        #pragma unroll
        for (int nt = 0; nt < 8; nt++) {
            sc[nt][0] = __expf(sc[nt][0] - mn_lo);
            sc[nt][1] = __expf(sc[nt][1] - mn_lo);
            sc[nt][2] = __expf(sc[nt][2] - mn_hi);
            sc[nt][3] = __expf(sc[nt][3] - mn_hi);
            s_lo += sc[nt][0] + sc[nt][1];
            s_hi += sc[nt][2] + sc[nt][3];
        }
        s_lo += __shfl_xor_sync(0xffffffffu, s_lo, 1);
        s_lo += __shfl_xor_sync(0xffffffffu, s_lo, 2);
        s_hi += __shfl_xor_sync(0xffffffffu, s_hi, 1);
        s_hi += __shfl_xor_sync(0xffffffffu, s_hi, 2);
        l_lo = l_lo * al_lo + s_lo;
        l_hi = l_hi * al_hi + s_hi;

        #pragma unroll
        for (int nt = 0; nt < 16; nt++) {
            Oa[nt][0] *= al_lo; Oa[nt][1] *= al_lo;
            Oa[nt][2] *= al_hi; Oa[nt][3] *= al_hi;
        }

        // ---- Stage P to smem (C-layout -> A-layout conversion) ----
        #pragma unroll
        for (int nt = 0; nt < 8; nt++) {
            int col = nt * 8 + 2 * t;
            Pw[g * PSTR + col]           = f2tf(sc[nt][0]);
            Pw[g * PSTR + col + 1]       = f2tf(sc[nt][1]);
            Pw[(g + 8) * PSTR + col]     = f2tf(sc[nt][2]);
            Pw[(g + 8) * PSTR + col + 1] = f2tf(sc[nt][3]);
        }
        __syncwarp();

        // ---- O += P V  (16x128 per warp) ----
        #pragma unroll
        for (int ks = 0; ks < 8; ks++) {
            unsigned a[4];
            int c0 = ks * 8 + t;
            a[0] = Pw[g * PSTR + c0];
            a[1] = Pw[(g + 8) * PSTR + c0];
            a[2] = Pw[g * PSTR + c0 + 4];
            a[3] = Pw[(g + 8) * PSTR + c0 + 4];
            #pragma unroll
            for (int nt = 0; nt < 16; nt++) {
                unsigned bb[2];
                bb[0] = Vu[(ks * 8 + t) * VSTR + nt * 8 + g];
                bb[1] = Vu[(ks * 8 + t + 4) * VSTR + nt * 8 + g];
                mma8(Oa[nt], a, bb);
            }
        }
        __syncwarp();   // P reads done before next iteration's stores
    }

    // ---- Epilogue: normalize and store ----
    const float inv_lo = 1.f / l_lo;
    const float inv_hi = 1.f / l_hi;
    float* og = Out + (b * S + qw) * (NH * HD) + h * HD;
    #pragma unroll
    for (int nt = 0; nt < 16; nt++) {
        int col = nt * 8 + 2 * t;
        float2 lo = make_float2(Oa[nt][0] * inv_lo, Oa[nt][1] * inv_lo);
        float2 hi = make_float2(Oa[nt][2] * inv_hi, Oa[nt][3] * inv_hi);
        *reinterpret_cast<float2*>(og + g * (NH * HD) + col) = lo;
        *reinterpret_cast<float2*>(og + (g + 8) * (NH * HD) + col) = hi;
    }
}

}  // namespace

extern "C" void kernel_launch(void* const* d_in, const int* in_sizes, int n_in,
                              void* d_out, int out_size) {
    const float* q = (const float*)d_in[0];
    const float* k = (const float*)d_in[1];
    const float* v = (const float*)d_in[2];
    float* out = (float*)d_out;

    const int smem_bytes = SMEM_FLOATS * (int)sizeof(float);  // 171,008 B
    cudaFuncSetAttribute(fa_tf32_kernel,
                         cudaFuncAttributeMaxDynamicSharedMemorySize, smem_bytes);

    // grid: 16 q-blocks * 32 heads * 2 batches = 1024 CTAs
    fa_tf32_kernel<<<1024, 256, smem_bytes>>>(q, k, v, out);
}